// round 1
// baseline (speedup 1.0000x reference)
#include <cuda_runtime.h>
#include <cuda_bf16.h>
#include <float.h>
#include <math.h>

#define N_NODES 131072
#define C_DIM   128
#define B_SEG   1024
#define H_DIM   128
#define TPB     256
#define TILE_N  128

__device__ float g_v[N_NODES];

// ---------------------------------------------------------------------------
// Kernel 1: per-node readout v[n] = lin + relu(x3 @ W1 + b1) @ W2 + b2 + sum(b_lins)
// ---------------------------------------------------------------------------
__global__ __launch_bounds__(TPB, 1)
void k_node(const float4* __restrict__ emb4,     // [N*C] float4 (r=0..3)
            const float*  __restrict__ W_lins,   // [3][128]
            const float*  __restrict__ b_lins,   // [3]
            const float*  __restrict__ W1,       // [128][128] (C,H)
            const float*  __restrict__ b1,       // [128]
            const float*  __restrict__ W2,       // [128]
            const float*  __restrict__ b2)       // [1]
{
    extern __shared__ float smem[];
    float* x3s   = smem;               // [128][132]
    float* w1s   = x3s + 128 * 132;    // [128][128]  w1s[c*128+h]
    float* lins4 = w1s + 128 * 128;    // [128][4] per-warp-group lin partials
    float* wl    = lins4 + 512;        // [3][128]
    float* b1s   = wl + 384;           // [128]
    float* w2s   = b1s + 128;          // [128]

    const int tid  = threadIdx.x;
    const int lane = tid & 31;
    const int warp = tid >> 5;
    const int n0   = blockIdx.x * TILE_N;

    // stage weights
    for (int i = tid; i < 128 * 128; i += TPB) w1s[i] = W1[i];
    for (int i = tid; i < 384; i += TPB)       wl[i]  = W_lins[i];
    if (tid < 128) { b1s[tid] = b1[tid]; w2s[tid] = W2[tid]; }
    __syncthreads();

    // ---- load embedding tile (coalesced float4), fold lin, stage x3 ----
    // idx = k*256 + tid; n = idx>>7 (all lanes of a warp share n), c = idx&127
    #pragma unroll 4
    for (int k = 0; k < 64; ++k) {
        int idx = k * TPB + tid;
        int n = idx >> 7;
        int c = idx & 127;
        float4 x = emb4[(size_t)(n0 + n) * 128 + c];
        x3s[n * 132 + c] = x.w;
        float p = x.x * wl[c] + x.y * wl[128 + c] + x.z * wl[256 + c];
        p += __shfl_xor_sync(0xffffffffu, p, 16);
        p += __shfl_xor_sync(0xffffffffu, p, 8);
        p += __shfl_xor_sync(0xffffffffu, p, 4);
        p += __shfl_xor_sync(0xffffffffu, p, 2);
        p += __shfl_xor_sync(0xffffffffu, p, 1);
        if (lane == 0) lins4[n * 4 + (warp & 3)] = p;   // unique (n, slot) per write
    }
    __syncthreads();

    // ---- register-tiled GEMM: 128 nodes x 128 h, 8x8 per thread ----
    const int tg = tid >> 4;        // node group 0..15
    const int th = tid & 15;        // h group 0..15
    const int nbase = tg * 8;
    const int hbase = th * 8;

    float acc[8][8];
    #pragma unroll
    for (int i = 0; i < 8; ++i)
        #pragma unroll
        for (int j = 0; j < 8; ++j) acc[i][j] = 0.f;

    for (int c = 0; c < 128; c += 4) {
        float4 a4[8];
        #pragma unroll
        for (int i = 0; i < 8; ++i)
            a4[i] = *(const float4*)&x3s[(nbase + i) * 132 + c];
        #pragma unroll
        for (int cc = 0; cc < 4; ++cc) {
            float4 bb0 = *(const float4*)&w1s[(c + cc) * 128 + hbase];
            float4 bb1 = *(const float4*)&w1s[(c + cc) * 128 + hbase + 4];
            float bfr[8] = {bb0.x, bb0.y, bb0.z, bb0.w, bb1.x, bb1.y, bb1.z, bb1.w};
            #pragma unroll
            for (int i = 0; i < 8; ++i) {
                float av = (cc == 0) ? a4[i].x : (cc == 1) ? a4[i].y
                         : (cc == 2) ? a4[i].z : a4[i].w;
                #pragma unroll
                for (int j = 0; j < 8; ++j)
                    acc[i][j] = fmaf(av, bfr[j], acc[i][j]);
            }
        }
    }

    // ---- epilogue: relu + W2 contraction, reduce over 16 h-groups ----
    float nl[8];
    #pragma unroll
    for (int i = 0; i < 8; ++i) {
        float s = 0.f;
        #pragma unroll
        for (int j = 0; j < 8; ++j) {
            float h = acc[i][j] + b1s[hbase + j];
            h = fmaxf(h, 0.f);
            s = fmaf(h, w2s[hbase + j], s);
        }
        nl[i] = s;
    }
    #pragma unroll
    for (int i = 0; i < 8; ++i) {
        nl[i] += __shfl_xor_sync(0xffffffffu, nl[i], 8);
        nl[i] += __shfl_xor_sync(0xffffffffu, nl[i], 4);
        nl[i] += __shfl_xor_sync(0xffffffffu, nl[i], 2);
        nl[i] += __shfl_xor_sync(0xffffffffu, nl[i], 1);
    }
    if (th == 0) {
        float bsum = b_lins[0] + b_lins[1] + b_lins[2];
        float b2v  = b2[0];
        #pragma unroll
        for (int i = 0; i < 8; ++i) {
            int n = nbase + i;
            float lin = lins4[n * 4 + 0] + lins4[n * 4 + 1] +
                        lins4[n * 4 + 2] + lins4[n * 4 + 3];
            g_v[n0 + n] = lin + bsum + nl[i] + b2v;
        }
    }
}

// ---------------------------------------------------------------------------
// Kernel 2: per-segment aggregation (sort + stats + quantiles) + final MLP
// ---------------------------------------------------------------------------
#define CAP 1024

__device__ __forceinline__ int lower_bound_i(const int* __restrict__ a, int n, int key)
{
    int lo = 0, hi = n;
    while (lo < hi) {
        int mid = (lo + hi) >> 1;
        if (a[mid] < key) lo = mid + 1; else hi = mid;
    }
    return lo;
}

__global__ __launch_bounds__(TPB, 4)
void k_agg(const int*   __restrict__ batch,
           const float* __restrict__ Wm1,   // [12][128]
           const float* __restrict__ bm1,   // [128]
           const float* __restrict__ Wm2,   // [128]
           const float* __restrict__ bm2,   // [1]
           float* __restrict__ out)
{
    __shared__ float sv[CAP];
    __shared__ float red[TPB];
    __shared__ float agg[12];
    __shared__ int   s_se[2];

    const int b   = blockIdx.x;
    const int tid = threadIdx.x;

    if (tid < 2) s_se[tid] = lower_bound_i(batch, N_NODES, b + tid);
    __syncthreads();
    const int start = s_se[0];
    const int cnt   = s_se[1] - s_se[0];

    if (cnt > 0) {
        for (int i = tid; i < CAP; i += TPB)
            sv[i] = (i < cnt) ? g_v[start + i] : FLT_MAX;
        __syncthreads();

        // bitonic sort of CAP elements
        for (int ksz = 2; ksz <= CAP; ksz <<= 1) {
            for (int j = ksz >> 1; j > 0; j >>= 1) {
                for (int i = tid; i < CAP; i += TPB) {
                    int p = i ^ j;
                    if (p > i) {
                        bool up = ((i & ksz) == 0);
                        float x = sv[i], y = sv[p];
                        if (up ? (x > y) : (x < y)) { sv[i] = y; sv[p] = x; }
                    }
                }
                __syncthreads();
            }
        }

        // mean via block reduce
        float ls = 0.f;
        for (int i = tid; i < cnt; i += TPB) ls += sv[i];
        red[tid] = ls;
        __syncthreads();
        for (int s = TPB >> 1; s > 0; s >>= 1) {
            if (tid < s) red[tid] += red[tid + s];
            __syncthreads();
        }
        if (tid == 0) agg[0] = red[0] / (float)cnt;
        if (tid == 1) agg[1] = sv[cnt - 1];       // max
        if (tid == 2) agg[2] = sv[0];             // min
        if (tid < 9) {
            float q    = (float)(tid + 1) * 0.1f;
            float pos  = q * (float)(cnt - 1);
            float f    = floorf(pos);
            float frac = pos - f;
            int lo = (int)f;
            if (lo > cnt - 1) lo = cnt - 1;
            if (lo < 0) lo = 0;
            int hi = lo + 1;
            if (hi > cnt - 1) hi = cnt - 1;
            agg[3 + tid] = sv[lo] + frac * (sv[hi] - sv[lo]);
        }
    } else {
        if (tid < 12) agg[tid] = 0.f;
    }
    __syncthreads();

    // MLP: relu(agg @ Wm1 + bm1) @ Wm2 + bm2
    float contrib = 0.f;
    if (tid < H_DIM) {
        float hj = bm1[tid];
        #pragma unroll
        for (int i = 0; i < 12; ++i)
            hj = fmaf(agg[i], Wm1[i * H_DIM + tid], hj);
        hj = fmaxf(hj, 0.f);
        contrib = hj * Wm2[tid];
    }
    red[tid] = contrib;
    __syncthreads();
    for (int s = TPB >> 1; s > 0; s >>= 1) {
        if (tid < s) red[tid] += red[tid + s];
        __syncthreads();
    }
    if (tid == 0) out[b] = red[0] + bm2[0];
}

// ---------------------------------------------------------------------------
extern "C" void kernel_launch(void* const* d_in, const int* in_sizes, int n_in,
                              void* d_out, int out_size)
{
    const float4* emb4   = (const float4*)d_in[0];
    const int*    batch  = (const int*)  d_in[1];
    const float*  W_lins = (const float*)d_in[2];
    const float*  b_lins = (const float*)d_in[3];
    const float*  W1     = (const float*)d_in[4];
    const float*  b1     = (const float*)d_in[5];
    const float*  W2     = (const float*)d_in[6];
    const float*  b2     = (const float*)d_in[7];
    const float*  Wm1    = (const float*)d_in[8];
    const float*  bm1    = (const float*)d_in[9];
    const float*  Wm2    = (const float*)d_in[10];
    const float*  bm2    = (const float*)d_in[11];
    float* out = (float*)d_out;

    const size_t smem_k1 = (size_t)(128 * 132 + 128 * 128 + 512 + 384 + 128 + 128) * sizeof(float);
    cudaFuncSetAttribute(k_node, cudaFuncAttributeMaxDynamicSharedMemorySize, (int)smem_k1);

    k_node<<<N_NODES / TILE_N, TPB, smem_k1>>>(emb4, W_lins, b_lins, W1, b1, W2, b2);
    k_agg<<<B_SEG, TPB>>>(batch, Wm1, bm1, Wm2, bm2, out);
}

// round 5
// speedup vs baseline: 2.1774x; 2.1774x over previous
#include <cuda_runtime.h>
#include <cuda_bf16.h>
#include <float.h>
#include <math.h>
#include <cstdint>

#define N_NODES 131072
#define B_SEG   1024
#define H_DIM   128
#define TPB     256
#define TILE_N  128

// Both tiles: [128 rows][136 halves] -> 272 B row stride (16B-aligned, 17x16B)
#define A_STRIDE 136
#define B_STRIDE 136

__device__ float g_v[N_NODES];
__device__ __align__(16) __nv_bfloat16 g_Bh[128 * B_STRIDE];   // W1 hi, padded [c][h]
__device__ __align__(16) __nv_bfloat16 g_Bl[128 * B_STRIDE];   // W1 lo, padded [c][h]

// SMEM layout (bytes)
static constexpr int SM_AH  = 0;                          // 128*136*2 = 34816
static constexpr int SM_AL  = 34816;
static constexpr int SM_BH  = 69632;
static constexpr int SM_BL  = 104448;
static constexpr int SM_FLT = 139264;
// floats: lins[128], ps[512], b1s[128], w2s[128] = 896 floats
static constexpr int SMEM_K1 = SM_FLT + 896 * 4;          // 142848

// ---------------------------------------------------------------------------
__device__ __forceinline__ uint32_t smem_u32(const void* p) {
    uint32_t a;
    asm("{ .reg .u64 t; cvta.to.shared.u64 t, %1; cvt.u32.u64 %0, t; }"
        : "=r"(a) : "l"(p));
    return a;
}

__device__ __forceinline__ void ldsm_x4(uint32_t* r, uint32_t a) {
    asm volatile("ldmatrix.sync.aligned.m8n8.x4.shared.b16 {%0,%1,%2,%3}, [%4];"
                 : "=r"(r[0]), "=r"(r[1]), "=r"(r[2]), "=r"(r[3]) : "r"(a));
}

__device__ __forceinline__ void ldsm_x2t(uint32_t* r, uint32_t a) {
    asm volatile("ldmatrix.sync.aligned.m8n8.x2.trans.shared.b16 {%0,%1}, [%2];"
                 : "=r"(r[0]), "=r"(r[1]) : "r"(a));
}

__device__ __forceinline__ void mma16816(float* d, const uint32_t* a, const uint32_t* b) {
    asm volatile(
        "mma.sync.aligned.m16n8k16.row.col.f32.bf16.bf16.f32 "
        "{%0,%1,%2,%3}, {%4,%5,%6,%7}, {%8,%9}, {%0,%1,%2,%3};"
        : "+f"(d[0]), "+f"(d[1]), "+f"(d[2]), "+f"(d[3])
        : "r"(a[0]), "r"(a[1]), "r"(a[2]), "r"(a[3]), "r"(b[0]), "r"(b[1]));
}

// ---------------------------------------------------------------------------
// Prep: split W1 ([C][H] row-major == B[k][n]) into hi/lo bf16 padded images
// ---------------------------------------------------------------------------
__global__ void k_prep(const float* __restrict__ W1) {
    int idx = blockIdx.x * 256 + threadIdx.x;   // 16384 total
    int c = idx >> 7, h = idx & 127;
    float w = W1[idx];
    __nv_bfloat16 hi = __float2bfloat16(w);
    float rem = w - __bfloat162float(hi);
    g_Bh[c * B_STRIDE + h] = hi;
    g_Bl[c * B_STRIDE + h] = __float2bfloat16(rem);
}

// ---------------------------------------------------------------------------
// Kernel 1: node readout via mma.sync split-bf16 GEMM
// D = Ah@Bh + Al@Bh + Ah@Bl   (Al@Bl ~ 2^-18, dropped)
// ---------------------------------------------------------------------------
__global__ __launch_bounds__(TPB, 1)
void k_node(const float4* __restrict__ emb4,
            const float*  __restrict__ W_lins,
            const float*  __restrict__ b_lins,
            const float*  __restrict__ b1,
            const float*  __restrict__ W2,
            const float*  __restrict__ b2)
{
    extern __shared__ __align__(16) char smem[];
    char* Ah = smem + SM_AH;
    char* Al = smem + SM_AL;
    float* lins = (float*)(smem + SM_FLT);   // [128]
    float* ps   = lins + 128;                // [128][4]
    float* b1s  = ps + 512;                  // [128]
    float* w2s  = b1s + 128;                 // [128]

    const int tid  = threadIdx.x;
    const int lane = tid & 31;
    const int wid  = tid >> 5;
    const int n0   = blockIdx.x * TILE_N;
    const uint32_t sbase = smem_u32(smem);

    // W_lins into registers (no smem dependency)
    float wlr[3][4];
    #pragma unroll
    for (int r = 0; r < 3; ++r)
        #pragma unroll
        for (int cc = 0; cc < 4; ++cc)
            wlr[r][cc] = W_lins[r * 128 + cc * 32 + lane];

    if (tid < 128) { b1s[tid] = b1[tid]; w2s[tid] = W2[tid]; }
    {
        const float4* sh = (const float4*)g_Bh;
        const float4* sl = (const float4*)g_Bl;
        float4* dh = (float4*)(smem + SM_BH);
        float4* dl = (float4*)(smem + SM_BL);
        #pragma unroll 4
        for (int i = tid; i < 128 * B_STRIDE * 2 / 16; i += TPB) {
            dh[i] = sh[i]; dl[i] = sl[i];
        }
    }

    // ---- load embedding (coalesced float4), fold lin, stage x3 hi/lo ----
    for (int i = 0; i < 16; ++i) {
        int nloc = wid * 16 + i;
        float linp = 0.f;
        #pragma unroll
        for (int cc = 0; cc < 4; ++cc) {
            int c = cc * 32 + lane;
            float4 x = emb4[(size_t)(n0 + nloc) * 128 + c];
            linp = fmaf(x.x, wlr[0][cc], linp);
            linp = fmaf(x.y, wlr[1][cc], linp);
            linp = fmaf(x.z, wlr[2][cc], linp);
            __nv_bfloat16 hi = __float2bfloat16(x.w);
            float rem = x.w - __bfloat162float(hi);
            int off = (nloc * A_STRIDE + c) * 2;
            *(__nv_bfloat16*)(Ah + off) = hi;
            *(__nv_bfloat16*)(Al + off) = __float2bfloat16(rem);
        }
        linp += __shfl_xor_sync(0xffffffffu, linp, 16);
        linp += __shfl_xor_sync(0xffffffffu, linp, 8);
        linp += __shfl_xor_sync(0xffffffffu, linp, 4);
        linp += __shfl_xor_sync(0xffffffffu, linp, 2);
        linp += __shfl_xor_sync(0xffffffffu, linp, 1);
        if (lane == 0) lins[nloc] = linp;
    }
    __syncthreads();

    // ---- mma.sync GEMM: warp grid 2(M)x4(N), each warp 64 rows x 32 cols ----
    const int wm = (wid >> 2) * 64;
    const int wn = (wid & 3) * 32;
    const int lr = lane & 15;
    const int lk = (lane >> 4) * 8;

    float acc[4][4][4];
    #pragma unroll
    for (int mt = 0; mt < 4; ++mt)
        #pragma unroll
        for (int nt = 0; nt < 4; ++nt)
            #pragma unroll
            for (int r = 0; r < 4; ++r) acc[mt][nt][r] = 0.f;

    const uint32_t aAh = sbase + SM_AH;
    const uint32_t aAl = sbase + SM_AL;
    const uint32_t aBh = sbase + SM_BH;
    const uint32_t aBl = sbase + SM_BL;

    #pragma unroll
    for (int k0 = 0; k0 < 128; k0 += 16) {
        uint32_t bh[4][2], bl[4][2];
        #pragma unroll
        for (int nt = 0; nt < 4; ++nt) {
            uint32_t boff = (uint32_t)(((k0 + lr) * B_STRIDE + wn + nt * 8) * 2);
            ldsm_x2t(bh[nt], aBh + boff);
            ldsm_x2t(bl[nt], aBl + boff);
        }
        #pragma unroll
        for (int mt = 0; mt < 4; ++mt) {
            uint32_t aoff = (uint32_t)(((wm + mt * 16 + lr) * A_STRIDE + k0 + lk) * 2);
            uint32_t ah[4], al[4];
            ldsm_x4(ah, aAh + aoff);
            ldsm_x4(al, aAl + aoff);
            #pragma unroll
            for (int nt = 0; nt < 4; ++nt) {
                mma16816(acc[mt][nt], ah, bh[nt]);
                mma16816(acc[mt][nt], al, bh[nt]);
                mma16816(acc[mt][nt], ah, bl[nt]);
            }
        }
    }

    // ---- epilogue: relu + W2 contraction inside fragments ----
    const int gid = lane >> 2;
    const int tig = lane & 3;
    float rp[4][2];
    #pragma unroll
    for (int mt = 0; mt < 4; ++mt) { rp[mt][0] = 0.f; rp[mt][1] = 0.f; }

    #pragma unroll
    for (int mt = 0; mt < 4; ++mt)
        #pragma unroll
        for (int nt = 0; nt < 4; ++nt)
            #pragma unroll
            for (int r = 0; r < 4; ++r) {
                int col = wn + nt * 8 + tig * 2 + (r & 1);
                float hv = acc[mt][nt][r] + b1s[col];
                rp[mt][r >> 1] = fmaf(fmaxf(hv, 0.f), w2s[col], rp[mt][r >> 1]);
            }

    #pragma unroll
    for (int mt = 0; mt < 4; ++mt)
        #pragma unroll
        for (int h = 0; h < 2; ++h) {
            float s = rp[mt][h];
            s += __shfl_xor_sync(0xffffffffu, s, 1);
            s += __shfl_xor_sync(0xffffffffu, s, 2);
            if (tig == 0)
                ps[(wm + mt * 16 + gid + h * 8) * 4 + (wid & 3)] = s;
        }
    __syncthreads();

    if (tid < 128) {
        float cst = b_lins[0] + b_lins[1] + b_lins[2] + b2[0];
        g_v[n0 + tid] = lins[tid] + ps[tid * 4] + ps[tid * 4 + 1]
                      + ps[tid * 4 + 2] + ps[tid * 4 + 3] + cst;
    }
}

// ---------------------------------------------------------------------------
// Kernel 2: per-segment aggregation (pow2 bitonic sort) + final MLP
// ---------------------------------------------------------------------------
#define CAP 1024

__device__ __forceinline__ int lower_bound_i(const int* __restrict__ a, int n, int key)
{
    int lo = 0, hi = n;
    while (lo < hi) {
        int mid = (lo + hi) >> 1;
        if (a[mid] < key) lo = mid + 1; else hi = mid;
    }
    return lo;
}

__global__ __launch_bounds__(TPB, 4)
void k_agg(const int*   __restrict__ batch,
           const float* __restrict__ Wm1,
           const float* __restrict__ bm1,
           const float* __restrict__ Wm2,
           const float* __restrict__ bm2,
           float* __restrict__ out)
{
    __shared__ float sv[CAP];
    __shared__ float red[TPB];
    __shared__ float agg[12];
    __shared__ int   s_se[2];

    const int b   = blockIdx.x;
    const int tid = threadIdx.x;

    if (tid < 2) s_se[tid] = lower_bound_i(batch, N_NODES, b + tid);
    __syncthreads();
    const int start = s_se[0];
    const int cnt   = s_se[1] - s_se[0];

    if (cnt > 0) {
        int m = 1;
        while (m < cnt) m <<= 1;      // next pow2 <= CAP

        for (int i = tid; i < m; i += TPB)
            sv[i] = (i < cnt) ? g_v[start + i] : FLT_MAX;
        __syncthreads();

        for (int ksz = 2; ksz <= m; ksz <<= 1) {
            for (int j = ksz >> 1; j > 0; j >>= 1) {
                for (int i = tid; i < m; i += TPB) {
                    int p = i ^ j;
                    if (p > i) {
                        bool up = ((i & ksz) == 0);
                        float x = sv[i], y = sv[p];
                        if (up ? (x > y) : (x < y)) { sv[i] = y; sv[p] = x; }
                    }
                }
                __syncthreads();
            }
        }

        float ls = 0.f;
        for (int i = tid; i < cnt; i += TPB) ls += sv[i];
        red[tid] = ls;
        __syncthreads();
        for (int s = TPB >> 1; s > 0; s >>= 1) {
            if (tid < s) red[tid] += red[tid + s];
            __syncthreads();
        }
        if (tid == 0) agg[0] = red[0] / (float)cnt;
        if (tid == 1) agg[1] = sv[cnt - 1];
        if (tid == 2) agg[2] = sv[0];
        if (tid < 9) {
            float q    = (float)(tid + 1) * 0.1f;
            float pos  = q * (float)(cnt - 1);
            float f    = floorf(pos);
            float frac = pos - f;
            int lo = (int)f;
            if (lo > cnt - 1) lo = cnt - 1;
            if (lo < 0) lo = 0;
            int hi = lo + 1;
            if (hi > cnt - 1) hi = cnt - 1;
            agg[3 + tid] = sv[lo] + frac * (sv[hi] - sv[lo]);
        }
    } else {
        if (tid < 12) agg[tid] = 0.f;
    }
    __syncthreads();

    float contrib = 0.f;
    if (tid < H_DIM) {
        float hj = bm1[tid];
        #pragma unroll
        for (int i = 0; i < 12; ++i)
            hj = fmaf(agg[i], Wm1[i * H_DIM + tid], hj);
        hj = fmaxf(hj, 0.f);
        contrib = hj * Wm2[tid];
    }
    red[tid] = contrib;
    __syncthreads();
    for (int s = TPB >> 1; s > 0; s >>= 1) {
        if (tid < s) red[tid] += red[tid + s];
        __syncthreads();
    }
    if (tid == 0) out[b] = red[0] + bm2[0];
}

// ---------------------------------------------------------------------------
extern "C" void kernel_launch(void* const* d_in, const int* in_sizes, int n_in,
                              void* d_out, int out_size)
{
    const float4* emb4   = (const float4*)d_in[0];
    const int*    batch  = (const int*)  d_in[1];
    const float*  W_lins = (const float*)d_in[2];
    const float*  b_lins = (const float*)d_in[3];
    const float*  W1     = (const float*)d_in[4];
    const float*  b1     = (const float*)d_in[5];
    const float*  W2     = (const float*)d_in[6];
    const float*  b2     = (const float*)d_in[7];
    const float*  Wm1    = (const float*)d_in[8];
    const float*  bm1    = (const float*)d_in[9];
    const float*  Wm2    = (const float*)d_in[10];
    const float*  bm2    = (const float*)d_in[11];
    float* out = (float*)d_out;

    cudaFuncSetAttribute(k_node, cudaFuncAttributeMaxDynamicSharedMemorySize, SMEM_K1);

    k_prep<<<64, 256>>>(W1);
    k_node<<<N_NODES / TILE_N, TPB, SMEM_K1>>>(emb4, W_lins, b_lins, b1, W2, b2);
    k_agg<<<B_SEG, TPB>>>(batch, Wm1, bm1, Wm2, bm2, out);
}

// round 6
// speedup vs baseline: 2.7077x; 1.2435x over previous
#include <cuda_runtime.h>
#include <cuda_fp16.h>
#include <float.h>
#include <math.h>
#include <cstdint>

#define N_NODES 131072
#define B_SEG   1024
#define H_DIM   128
#define TPB     256
#define TILE_N  128

// Tiles: [128 rows][136 halves] -> 272 B row stride (16B-aligned, 17x16B units)
#define A_STRIDE 136
#define B_STRIDE 136

__device__ float g_v[N_NODES];

// SMEM layout (bytes)
static constexpr int SM_AH  = 0;                          // 128*136*2 = 34816
static constexpr int SM_AL  = 34816;
static constexpr int SM_BH  = 69632;
static constexpr int SM_FLT = 104448;
// floats: lins[128], ps[512], b1s[128], w2s[128] = 896 floats
static constexpr int SMEM_K1 = SM_FLT + 896 * 4;          // 108032  -> 2 CTAs/SM

// ---------------------------------------------------------------------------
__device__ __forceinline__ uint32_t smem_u32(const void* p) {
    uint32_t a;
    asm("{ .reg .u64 t; cvta.to.shared.u64 t, %1; cvt.u32.u64 %0, t; }"
        : "=r"(a) : "l"(p));
    return a;
}

__device__ __forceinline__ void ldsm_x4(uint32_t* r, uint32_t a) {
    asm volatile("ldmatrix.sync.aligned.m8n8.x4.shared.b16 {%0,%1,%2,%3}, [%4];"
                 : "=r"(r[0]), "=r"(r[1]), "=r"(r[2]), "=r"(r[3]) : "r"(a));
}

__device__ __forceinline__ void ldsm_x2t(uint32_t* r, uint32_t a) {
    asm volatile("ldmatrix.sync.aligned.m8n8.x2.trans.shared.b16 {%0,%1}, [%2];"
                 : "=r"(r[0]), "=r"(r[1]) : "r"(a));
}

__device__ __forceinline__ void mma16816(float* d, const uint32_t* a, const uint32_t* b) {
    asm volatile(
        "mma.sync.aligned.m16n8k16.row.col.f32.f16.f16.f32 "
        "{%0,%1,%2,%3}, {%4,%5,%6,%7}, {%8,%9}, {%0,%1,%2,%3};"
        : "+f"(d[0]), "+f"(d[1]), "+f"(d[2]), "+f"(d[3])
        : "r"(a[0]), "r"(a[1]), "r"(a[2]), "r"(a[3]), "r"(b[0]), "r"(b[1]));
}

// ---------------------------------------------------------------------------
// Kernel 1: node readout via mma.sync fp16 2-term split GEMM
//   D = Ah@Bh + Al@Bh   (A-side exact; B fp16-rounded, rel ~2^-12)
// ---------------------------------------------------------------------------
__global__ __launch_bounds__(TPB, 2)
void k_node(const float4* __restrict__ emb4,
            const float*  __restrict__ W_lins,
            const float*  __restrict__ b_lins,
            const float*  __restrict__ W1,
            const float*  __restrict__ b1,
            const float*  __restrict__ W2,
            const float*  __restrict__ b2)
{
    extern __shared__ __align__(16) char smem[];
    char* Ah = smem + SM_AH;
    char* Al = smem + SM_AL;
    char* Bh = smem + SM_BH;
    float* lins = (float*)(smem + SM_FLT);   // [128]
    float* ps   = lins + 128;                // [128][4]
    float* b1s  = ps + 512;                  // [128]
    float* w2s  = b1s + 128;                 // [128]

    const int tid  = threadIdx.x;
    const int lane = tid & 31;
    const int wid  = tid >> 5;
    const int n0   = blockIdx.x * TILE_N;
    const uint32_t sbase = smem_u32(smem);

    // W_lins into registers (no smem dependency)
    float wlr[3][4];
    #pragma unroll
    for (int r = 0; r < 3; ++r)
        #pragma unroll
        for (int cc = 0; cc < 4; ++cc)
            wlr[r][cc] = W_lins[r * 128 + cc * 32 + lane];

    if (tid < 128) { b1s[tid] = b1[tid]; w2s[tid] = W2[tid]; }

    // stage W1 -> fp16 Bh tile ([c][h], padded), straight from L2
    #pragma unroll 4
    for (int i = tid; i < 128 * 128; i += TPB) {
        int c = i >> 7, h = i & 127;
        *(__half*)(Bh + (c * B_STRIDE + h) * 2) = __float2half_rn(W1[i]);
    }

    // ---- load embedding (coalesced float4), fold lin, stage x3 hi/lo ----
    for (int i = 0; i < 16; ++i) {
        int nloc = wid * 16 + i;
        float linp = 0.f;
        #pragma unroll
        for (int cc = 0; cc < 4; ++cc) {
            int c = cc * 32 + lane;
            float4 x = emb4[(size_t)(n0 + nloc) * 128 + c];
            linp = fmaf(x.x, wlr[0][cc], linp);
            linp = fmaf(x.y, wlr[1][cc], linp);
            linp = fmaf(x.z, wlr[2][cc], linp);
            __half hi = __float2half_rn(x.w);
            float rem = x.w - __half2float(hi);
            int off = (nloc * A_STRIDE + c) * 2;
            *(__half*)(Ah + off) = hi;
            *(__half*)(Al + off) = __float2half_rn(rem);
        }
        linp += __shfl_xor_sync(0xffffffffu, linp, 16);
        linp += __shfl_xor_sync(0xffffffffu, linp, 8);
        linp += __shfl_xor_sync(0xffffffffu, linp, 4);
        linp += __shfl_xor_sync(0xffffffffu, linp, 2);
        linp += __shfl_xor_sync(0xffffffffu, linp, 1);
        if (lane == 0) lins[nloc] = linp;
    }
    __syncthreads();

    // ---- mma.sync GEMM: warp grid 2(M)x4(N), each warp 64 rows x 32 cols ----
    const int wm = (wid >> 2) * 64;
    const int wn = (wid & 3) * 32;
    const int lr = lane & 15;
    const int lk = (lane >> 4) * 8;

    float acc[4][4][4];
    #pragma unroll
    for (int mt = 0; mt < 4; ++mt)
        #pragma unroll
        for (int nt = 0; nt < 4; ++nt)
            #pragma unroll
            for (int r = 0; r < 4; ++r) acc[mt][nt][r] = 0.f;

    const uint32_t aAh = sbase + SM_AH;
    const uint32_t aAl = sbase + SM_AL;
    const uint32_t aBh = sbase + SM_BH;

    #pragma unroll
    for (int k0 = 0; k0 < 128; k0 += 16) {
        uint32_t bh[4][2];
        #pragma unroll
        for (int nt = 0; nt < 4; ++nt) {
            uint32_t boff = (uint32_t)(((k0 + lr) * B_STRIDE + wn + nt * 8) * 2);
            ldsm_x2t(bh[nt], aBh + boff);
        }
        #pragma unroll
        for (int mt = 0; mt < 4; ++mt) {
            uint32_t aoff = (uint32_t)(((wm + mt * 16 + lr) * A_STRIDE + k0 + lk) * 2);
            uint32_t ah[4], al[4];
            ldsm_x4(ah, aAh + aoff);
            ldsm_x4(al, aAl + aoff);
            #pragma unroll
            for (int nt = 0; nt < 4; ++nt) {
                mma16816(acc[mt][nt], ah, bh[nt]);
                mma16816(acc[mt][nt], al, bh[nt]);
            }
        }
    }

    // ---- epilogue: relu + W2 contraction inside fragments ----
    const int gid = lane >> 2;
    const int tig = lane & 3;
    float rp[4][2];
    #pragma unroll
    for (int mt = 0; mt < 4; ++mt) { rp[mt][0] = 0.f; rp[mt][1] = 0.f; }

    #pragma unroll
    for (int mt = 0; mt < 4; ++mt)
        #pragma unroll
        for (int nt = 0; nt < 4; ++nt)
            #pragma unroll
            for (int r = 0; r < 4; ++r) {
                int col = wn + nt * 8 + tig * 2 + (r & 1);
                float hv = acc[mt][nt][r] + b1s[col];
                rp[mt][r >> 1] = fmaf(fmaxf(hv, 0.f), w2s[col], rp[mt][r >> 1]);
            }

    #pragma unroll
    for (int mt = 0; mt < 4; ++mt)
        #pragma unroll
        for (int h = 0; h < 2; ++h) {
            float s = rp[mt][h];
            s += __shfl_xor_sync(0xffffffffu, s, 1);
            s += __shfl_xor_sync(0xffffffffu, s, 2);
            if (tig == 0)
                ps[(wm + mt * 16 + gid + h * 8) * 4 + (wid & 3)] = s;
        }
    __syncthreads();

    if (tid < 128) {
        float cst = b_lins[0] + b_lins[1] + b_lins[2] + b2[0];
        g_v[n0 + tid] = lins[tid] + ps[tid * 4] + ps[tid * 4 + 1]
                      + ps[tid * 4 + 2] + ps[tid * 4 + 3] + cst;
    }
}

// ---------------------------------------------------------------------------
// Kernel 2: per-segment aggregation (pow2 bitonic sort) + final MLP
// ---------------------------------------------------------------------------
#define CAP 1024

__device__ __forceinline__ int lower_bound_i(const int* __restrict__ a, int n, int key)
{
    int lo = 0, hi = n;
    while (lo < hi) {
        int mid = (lo + hi) >> 1;
        if (a[mid] < key) lo = mid + 1; else hi = mid;
    }
    return lo;
}

__global__ __launch_bounds__(TPB, 4)
void k_agg(const int*   __restrict__ batch,
           const float* __restrict__ Wm1,
           const float* __restrict__ bm1,
           const float* __restrict__ Wm2,
           const float* __restrict__ bm2,
           float* __restrict__ out)
{
    __shared__ float sv[CAP];
    __shared__ float red[TPB];
    __shared__ float agg[12];
    __shared__ int   s_se[2];

    const int b   = blockIdx.x;
    const int tid = threadIdx.x;

    if (tid < 2) s_se[tid] = lower_bound_i(batch, N_NODES, b + tid);
    __syncthreads();
    const int start = s_se[0];
    const int cnt   = s_se[1] - s_se[0];

    if (cnt > 0) {
        int m = 1;
        while (m < cnt) m <<= 1;      // next pow2 <= CAP

        for (int i = tid; i < m; i += TPB)
            sv[i] = (i < cnt) ? g_v[start + i] : FLT_MAX;
        __syncthreads();

        for (int ksz = 2; ksz <= m; ksz <<= 1) {
            for (int j = ksz >> 1; j > 0; j >>= 1) {
                for (int i = tid; i < m; i += TPB) {
                    int p = i ^ j;
                    if (p > i) {
                        bool up = ((i & ksz) == 0);
                        float x = sv[i], y = sv[p];
                        if (up ? (x > y) : (x < y)) { sv[i] = y; sv[p] = x; }
                    }
                }
                __syncthreads();
            }
        }

        float ls = 0.f;
        for (int i = tid; i < cnt; i += TPB) ls += sv[i];
        red[tid] = ls;
        __syncthreads();
        for (int s = TPB >> 1; s > 0; s >>= 1) {
            if (tid < s) red[tid] += red[tid + s];
            __syncthreads();
        }
        if (tid == 0) agg[0] = red[0] / (float)cnt;
        if (tid == 1) agg[1] = sv[cnt - 1];
        if (tid == 2) agg[2] = sv[0];
        if (tid < 9) {
            float q    = (float)(tid + 1) * 0.1f;
            float pos  = q * (float)(cnt - 1);
            float f    = floorf(pos);
            float frac = pos - f;
            int lo = (int)f;
            if (lo > cnt - 1) lo = cnt - 1;
            if (lo < 0) lo = 0;
            int hi = lo + 1;
            if (hi > cnt - 1) hi = cnt - 1;
            agg[3 + tid] = sv[lo] + frac * (sv[hi] - sv[lo]);
        }
    } else {
        if (tid < 12) agg[tid] = 0.f;
    }
    __syncthreads();

    float contrib = 0.f;
    if (tid < H_DIM) {
        float hj = bm1[tid];
        #pragma unroll
        for (int i = 0; i < 12; ++i)
            hj = fmaf(agg[i], Wm1[i * H_DIM + tid], hj);
        hj = fmaxf(hj, 0.f);
        contrib = hj * Wm2[tid];
    }
    red[tid] = contrib;
    __syncthreads();
    for (int s = TPB >> 1; s > 0; s >>= 1) {
        if (tid < s) red[tid] += red[tid + s];
        __syncthreads();
    }
    if (tid == 0) out[b] = red[0] + bm2[0];
}

// ---------------------------------------------------------------------------
extern "C" void kernel_launch(void* const* d_in, const int* in_sizes, int n_in,
                              void* d_out, int out_size)
{
    const float4* emb4   = (const float4*)d_in[0];
    const int*    batch  = (const int*)  d_in[1];
    const float*  W_lins = (const float*)d_in[2];
    const float*  b_lins = (const float*)d_in[3];
    const float*  W1     = (const float*)d_in[4];
    const float*  b1     = (const float*)d_in[5];
    const float*  W2     = (const float*)d_in[6];
    const float*  b2     = (const float*)d_in[7];
    const float*  Wm1    = (const float*)d_in[8];
    const float*  bm1    = (const float*)d_in[9];
    const float*  Wm2    = (const float*)d_in[10];
    const float*  bm2    = (const float*)d_in[11];
    float* out = (float*)d_out;

    cudaFuncSetAttribute(k_node, cudaFuncAttributeMaxDynamicSharedMemorySize, SMEM_K1);

    k_node<<<N_NODES / TILE_N, TPB, SMEM_K1>>>(emb4, W_lins, b_lins, W1, b1, W2, b2);
    k_agg<<<B_SEG, TPB>>>(batch, Wm1, bm1, Wm2, bm2, out);
}

// round 7
// speedup vs baseline: 3.9123x; 1.4449x over previous
#include <cuda_runtime.h>
#include <cuda_fp16.h>
#include <float.h>
#include <math.h>
#include <cstdint>

#define N_NODES 131072
#define B_SEG   1024
#define H_DIM   128
#define TILE_N  128
#define NTILES  (N_NODES / TILE_N)

// Tiles: [128 rows][136 halves] -> 272 B row stride (16B-aligned, 17x16B units)
#define A_STRIDE 136
#define B_STRIDE 136

__device__ float g_v[N_NODES];

// ---- k_node smem layout (bytes) ----
static constexpr int STAGE   = 69632;              // Ah(34816) + Al(34816) per stage
static constexpr int SM_B    = 2 * STAGE;          // 139264
static constexpr int SM_FLT  = SM_B + 34816;       // 174080
// floats: lins[2][128], ps[512], b1s[128], w2s[128] = 1024 floats
static constexpr int SMEM_K1 = SM_FLT + 1024 * 4;  // 178176

// ---------------------------------------------------------------------------
__device__ __forceinline__ uint32_t smem_u32(const void* p) {
    uint32_t a;
    asm("{ .reg .u64 t; cvta.to.shared.u64 t, %1; cvt.u32.u64 %0, t; }"
        : "=r"(a) : "l"(p));
    return a;
}

__device__ __forceinline__ void bar_sync(int id, int cnt) {
    asm volatile("bar.sync %0, %1;" :: "r"(id), "r"(cnt) : "memory");
}
__device__ __forceinline__ void bar_arrive(int id, int cnt) {
    asm volatile("bar.arrive %0, %1;" :: "r"(id), "r"(cnt) : "memory");
}

__device__ __forceinline__ void ldsm_x4(uint32_t* r, uint32_t a) {
    asm volatile("ldmatrix.sync.aligned.m8n8.x4.shared.b16 {%0,%1,%2,%3}, [%4];"
                 : "=r"(r[0]), "=r"(r[1]), "=r"(r[2]), "=r"(r[3]) : "r"(a));
}
__device__ __forceinline__ void ldsm_x2t(uint32_t* r, uint32_t a) {
    asm volatile("ldmatrix.sync.aligned.m8n8.x2.trans.shared.b16 {%0,%1}, [%2];"
                 : "=r"(r[0]), "=r"(r[1]) : "r"(a));
}
__device__ __forceinline__ void mma16816(float* d, const uint32_t* a, const uint32_t* b) {
    asm volatile(
        "mma.sync.aligned.m16n8k16.row.col.f32.f16.f16.f32 "
        "{%0,%1,%2,%3}, {%4,%5,%6,%7}, {%8,%9}, {%0,%1,%2,%3};"
        : "+f"(d[0]), "+f"(d[1]), "+f"(d[2]), "+f"(d[3])
        : "r"(a[0]), "r"(a[1]), "r"(a[2]), "r"(a[3]), "r"(b[0]), "r"(b[1]));
}

// ---------------------------------------------------------------------------
// Kernel 1: persistent warp-specialized node readout
//   producers (warps 0-7): load embedding, fold lin, split fp16 -> A ring
//   consumers (warps 8-15): mma.sync GEMM (D = Ah@Bh + Al@Bh), relu+W2 epilogue
// ---------------------------------------------------------------------------
__global__ __launch_bounds__(512, 1)
void k_node(const float4* __restrict__ emb4,
            const float*  __restrict__ W_lins,
            const float*  __restrict__ b_lins,
            const float*  __restrict__ W1,
            const float*  __restrict__ b1,
            const float*  __restrict__ W2,
            const float*  __restrict__ b2)
{
    extern __shared__ __align__(16) char smem[];
    char*  Bh   = smem + SM_B;
    float* lins = (float*)(smem + SM_FLT);   // [2][128]
    float* ps   = lins + 256;                // [128][4]
    float* b1s  = ps + 512;                  // [128]
    float* w2s  = b1s + 128;                 // [128]

    const int tid  = threadIdx.x;
    const int lane = tid & 31;
    const int wid  = tid >> 5;
    const bool producer = (wid < 8);
    const uint32_t sbase = smem_u32(smem);

    // ---- one-time staging: W1 -> fp16 B tile (float4 loads), b1s, w2s ----
    for (int i = tid; i < 128 * 128 / 4; i += 512) {
        float4 w = ((const float4*)W1)[i];
        int c  = i >> 5;
        int h4 = (i & 31) * 4;
        int off = (c * B_STRIDE + h4) * 2;
        *(__half2*)(Bh + off)     = __floats2half2_rn(w.x, w.y);
        *(__half2*)(Bh + off + 4) = __floats2half2_rn(w.z, w.w);
    }
    if (tid < 128) { b1s[tid] = b1[tid]; w2s[tid] = W2[tid]; }

    // producers: W_lins into registers
    float wlr[3][4];
    if (producer) {
        #pragma unroll
        for (int r = 0; r < 3; ++r)
            #pragma unroll
            for (int cc = 0; cc < 4; ++cc)
                wlr[r][cc] = W_lins[r * 128 + cc * 32 + lane];
    }
    const float cst = b_lins[0] + b_lins[1] + b_lins[2] + b2[0];
    __syncthreads();

    int it = 0;
    for (int t = blockIdx.x; t < NTILES; t += gridDim.x, ++it) {
        const int s  = it & 1;
        const int n0 = t * TILE_N;

        if (producer) {
            if (it >= 2) bar_sync(4 + s, 512);          // wait stage empty
            char* AhS = smem + s * STAGE;
            char* AlS = AhS + 34816;

            for (int ii = 0; ii < 16; ii += 2) {
                int nl0 = wid * 16 + ii;
                int nl1 = nl0 + 1;
                float4 x0[4], x1[4];
                #pragma unroll
                for (int cc = 0; cc < 4; ++cc)
                    x0[cc] = emb4[(size_t)(n0 + nl0) * 128 + cc * 32 + lane];
                #pragma unroll
                for (int cc = 0; cc < 4; ++cc)
                    x1[cc] = emb4[(size_t)(n0 + nl1) * 128 + cc * 32 + lane];

                float l0 = 0.f, l1 = 0.f;
                #pragma unroll
                for (int cc = 0; cc < 4; ++cc) {
                    int c = cc * 32 + lane;
                    l0 = fmaf(x0[cc].x, wlr[0][cc], l0);
                    l0 = fmaf(x0[cc].y, wlr[1][cc], l0);
                    l0 = fmaf(x0[cc].z, wlr[2][cc], l0);
                    __half h0 = __float2half_rn(x0[cc].w);
                    float r0 = x0[cc].w - __half2float(h0);
                    int o0 = (nl0 * A_STRIDE + c) * 2;
                    *(__half*)(AhS + o0) = h0;
                    *(__half*)(AlS + o0) = __float2half_rn(r0);

                    l1 = fmaf(x1[cc].x, wlr[0][cc], l1);
                    l1 = fmaf(x1[cc].y, wlr[1][cc], l1);
                    l1 = fmaf(x1[cc].z, wlr[2][cc], l1);
                    __half h1 = __float2half_rn(x1[cc].w);
                    float r1 = x1[cc].w - __half2float(h1);
                    int o1 = (nl1 * A_STRIDE + c) * 2;
                    *(__half*)(AhS + o1) = h1;
                    *(__half*)(AlS + o1) = __float2half_rn(r1);
                }
                #pragma unroll
                for (int d = 16; d > 0; d >>= 1) {
                    l0 += __shfl_xor_sync(0xffffffffu, l0, d);
                    l1 += __shfl_xor_sync(0xffffffffu, l1, d);
                }
                if (lane == 0) { lins[s * 128 + nl0] = l0; lins[s * 128 + nl1] = l1; }
            }
            __threadfence_block();
            bar_arrive(2 + s, 512);                     // signal stage full
        } else {
            bar_sync(2 + s, 512);                       // wait stage full

            const int cw = wid - 8;
            const int wm = (cw >> 2) * 64;
            const int wn = (cw & 3) * 32;
            const int lr = lane & 15;
            const int lk = (lane >> 4) * 8;

            float acc[4][4][4];
            #pragma unroll
            for (int mt = 0; mt < 4; ++mt)
                #pragma unroll
                for (int nt = 0; nt < 4; ++nt)
                    #pragma unroll
                    for (int r = 0; r < 4; ++r) acc[mt][nt][r] = 0.f;

            const uint32_t aAh = sbase + s * STAGE;
            const uint32_t aAl = aAh + 34816;
            const uint32_t aBh = sbase + SM_B;

            #pragma unroll
            for (int k0 = 0; k0 < 128; k0 += 16) {
                uint32_t bh[4][2];
                #pragma unroll
                for (int nt = 0; nt < 4; ++nt) {
                    uint32_t boff = (uint32_t)(((k0 + lr) * B_STRIDE + wn + nt * 8) * 2);
                    ldsm_x2t(bh[nt], aBh + boff);
                }
                #pragma unroll
                for (int mt = 0; mt < 4; ++mt) {
                    uint32_t aoff = (uint32_t)(((wm + mt * 16 + lr) * A_STRIDE + k0 + lk) * 2);
                    uint32_t ah[4], al[4];
                    ldsm_x4(ah, aAh + aoff);
                    ldsm_x4(al, aAl + aoff);
                    #pragma unroll
                    for (int nt = 0; nt < 4; ++nt) {
                        mma16816(acc[mt][nt], ah, bh[nt]);
                        mma16816(acc[mt][nt], al, bh[nt]);
                    }
                }
            }

            // epilogue: relu + W2 contraction inside fragments
            const int gid = lane >> 2;
            const int tig = lane & 3;
            float rp[4][2];
            #pragma unroll
            for (int mt = 0; mt < 4; ++mt) { rp[mt][0] = 0.f; rp[mt][1] = 0.f; }

            #pragma unroll
            for (int mt = 0; mt < 4; ++mt)
                #pragma unroll
                for (int nt = 0; nt < 4; ++nt)
                    #pragma unroll
                    for (int r = 0; r < 4; ++r) {
                        int col = wn + nt * 8 + tig * 2 + (r & 1);
                        float hv = acc[mt][nt][r] + b1s[col];
                        rp[mt][r >> 1] = fmaf(fmaxf(hv, 0.f), w2s[col], rp[mt][r >> 1]);
                    }

            #pragma unroll
            for (int mt = 0; mt < 4; ++mt)
                #pragma unroll
                for (int h = 0; h < 2; ++h) {
                    float sum = rp[mt][h];
                    sum += __shfl_xor_sync(0xffffffffu, sum, 1);
                    sum += __shfl_xor_sync(0xffffffffu, sum, 2);
                    if (tig == 0)
                        ps[(wm + mt * 16 + gid + h * 8) * 4 + (cw & 3)] = sum;
                }
            bar_sync(6, 256);                           // consumers only

            int ctid = tid - 256;
            if (ctid < 128) {
                g_v[n0 + ctid] = lins[s * 128 + ctid] + ps[ctid * 4] + ps[ctid * 4 + 1]
                               + ps[ctid * 4 + 2] + ps[ctid * 4 + 3] + cst;
            }
            bar_arrive(4 + s, 512);                     // signal stage empty
        }
    }
}

// ---------------------------------------------------------------------------
// Kernel 2: warp-per-segment register bitonic sort + stats + MLP
// ---------------------------------------------------------------------------
#define CAP 1024

__device__ __forceinline__ int lower_bound_i(const int* __restrict__ a, int n, int key)
{
    int lo = 0, hi = n;
    while (lo < hi) {
        int mid = (lo + hi) >> 1;
        if (a[mid] < key) lo = mid + 1; else hi = mid;
    }
    return lo;
}

__global__ __launch_bounds__(256, 4)
void k_agg(const int*   __restrict__ batch,
           const float* __restrict__ Wm1,
           const float* __restrict__ bm1,
           const float* __restrict__ Wm2,
           const float* __restrict__ bm2,
           float* __restrict__ out)
{
    __shared__ float ssort[8][256];
    __shared__ float sv[CAP];
    __shared__ float red[256];
    __shared__ float aggd[12];
    __shared__ int   dlist[8];
    __shared__ int   dcount;
    __shared__ int   s_se[2];

    const int tid  = threadIdx.x;
    const int lane = tid & 31;
    const int wid  = tid >> 5;
    const int seg  = blockIdx.x * 8 + wid;

    if (tid == 0) dcount = 0;
    __syncthreads();

    // per-warp segment bounds
    int lb = 0;
    if (lane < 2) lb = lower_bound_i(batch, N_NODES, seg + lane);
    int start = __shfl_sync(0xffffffffu, lb, 0);
    int cnt   = __shfl_sync(0xffffffffu, lb, 1) - start;

    if (cnt > 256) {
        if (lane == 0) { int p = atomicAdd(&dcount, 1); dlist[p] = wid; }
    } else {
        // load 8 elems/lane (coalesced; idx = r*32+lane), pad FLT_MAX
        float v[8];
        float sum = 0.f;
        #pragma unroll
        for (int r = 0; r < 8; ++r) {
            int i = r * 32 + lane;
            float x = (i < cnt) ? g_v[start + i] : FLT_MAX;
            v[r] = x;
            if (i < cnt) sum += x;
        }
        #pragma unroll
        for (int d = 16; d > 0; d >>= 1) sum += __shfl_xor_sync(0xffffffffu, sum, d);

        // fixed 256-element bitonic network: idx = r*32 + lane
        #pragma unroll
        for (int k = 2; k <= 256; k <<= 1) {
            #pragma unroll
            for (int j = k >> 1; j > 0; j >>= 1) {
                if (j >= 32) {
                    const int jr = j >> 5;
                    #pragma unroll
                    for (int r = 0; r < 8; ++r) {
                        if ((r & jr) == 0) {
                            int rp = r | jr;
                            bool up = (((r * 32) & k) == 0);
                            float a = v[r], b = v[rp];
                            float lo = fminf(a, b), hi = fmaxf(a, b);
                            v[r]  = up ? lo : hi;
                            v[rp] = up ? hi : lo;
                        }
                    }
                } else {
                    #pragma unroll
                    for (int r = 0; r < 8; ++r) {
                        float other = __shfl_xor_sync(0xffffffffu, v[r], j);
                        bool lower = (lane & j) == 0;
                        bool up = (k < 32) ? ((lane & k) == 0) : (((r * 32) & k) == 0);
                        v[r] = (up == lower) ? fminf(v[r], other) : fmaxf(v[r], other);
                    }
                }
            }
        }

        #pragma unroll
        for (int r = 0; r < 8; ++r) ssort[wid][r * 32 + lane] = v[r];
        __syncwarp();

        float agg[12];
        if (cnt > 0) {
            const float* sw = ssort[wid];
            agg[0] = sum / (float)cnt;
            agg[1] = sw[cnt - 1];
            agg[2] = sw[0];
            #pragma unroll
            for (int qi = 0; qi < 9; ++qi) {
                float q    = (float)(qi + 1) * 0.1f;
                float pos  = q * (float)(cnt - 1);
                float f    = floorf(pos);
                float frac = pos - f;
                int lo = (int)f;
                if (lo > cnt - 1) lo = cnt - 1;
                if (lo < 0) lo = 0;
                int hi = lo + 1;
                if (hi > cnt - 1) hi = cnt - 1;
                agg[3 + qi] = sw[lo] + frac * (sw[hi] - sw[lo]);
            }
        } else {
            #pragma unroll
            for (int i = 0; i < 12; ++i) agg[i] = 0.f;
        }

        // MLP in-warp: lane handles h = lane, +32, +64, +96
        float c = 0.f;
        #pragma unroll
        for (int hh = 0; hh < 4; ++hh) {
            int h = hh * 32 + lane;
            float hj = bm1[h];
            #pragma unroll
            for (int i = 0; i < 12; ++i)
                hj = fmaf(agg[i], Wm1[i * H_DIM + h], hj);
            c = fmaf(fmaxf(hj, 0.f), Wm2[h], c);
        }
        #pragma unroll
        for (int d = 16; d > 0; d >>= 1) c += __shfl_xor_sync(0xffffffffu, c, d);
        if (lane == 0) out[seg] = c + bm2[0];
    }
    __syncthreads();

    // ---- deferred (cnt > 256) segments: block-wide bitonic path ----
    for (int d = 0; d < dcount; ++d) {
        const int w = dlist[d];
        const int dseg = blockIdx.x * 8 + w;

        if (tid < 2) s_se[tid] = lower_bound_i(batch, N_NODES, dseg + tid);
        __syncthreads();
        const int dstart = s_se[0];
        const int dcnt   = s_se[1] - s_se[0];

        int m = 1;
        while (m < dcnt) m <<= 1;
        if (m > CAP) m = CAP;

        for (int i = tid; i < m; i += 256)
            sv[i] = (i < dcnt && i < CAP) ? g_v[dstart + i] : FLT_MAX;
        __syncthreads();

        for (int ksz = 2; ksz <= m; ksz <<= 1) {
            for (int j = ksz >> 1; j > 0; j >>= 1) {
                for (int i = tid; i < m; i += 256) {
                    int p = i ^ j;
                    if (p > i) {
                        bool up = ((i & ksz) == 0);
                        float x = sv[i], y = sv[p];
                        if (up ? (x > y) : (x < y)) { sv[i] = y; sv[p] = x; }
                    }
                }
                __syncthreads();
            }
        }

        float ls = 0.f;
        for (int i = tid; i < dcnt; i += 256) ls += sv[i];
        red[tid] = ls;
        __syncthreads();
        for (int s = 128; s > 0; s >>= 1) {
            if (tid < s) red[tid] += red[tid + s];
            __syncthreads();
        }
        if (tid == 0) aggd[0] = red[0] / (float)dcnt;
        if (tid == 1) aggd[1] = sv[dcnt - 1];
        if (tid == 2) aggd[2] = sv[0];
        if (tid < 9) {
            float q    = (float)(tid + 1) * 0.1f;
            float pos  = q * (float)(dcnt - 1);
            float f    = floorf(pos);
            float frac = pos - f;
            int lo = (int)f;
            if (lo > dcnt - 1) lo = dcnt - 1;
            if (lo < 0) lo = 0;
            int hi = lo + 1;
            if (hi > dcnt - 1) hi = dcnt - 1;
            aggd[3 + tid] = sv[lo] + frac * (sv[hi] - sv[lo]);
        }
        __syncthreads();

        float contrib = 0.f;
        if (tid < H_DIM) {
            float hj = bm1[tid];
            #pragma unroll
            for (int i = 0; i < 12; ++i)
                hj = fmaf(aggd[i], Wm1[i * H_DIM + tid], hj);
            hj = fmaxf(hj, 0.f);
            contrib = hj * Wm2[tid];
        }
        red[tid] = contrib;
        __syncthreads();
        for (int s = 128; s > 0; s >>= 1) {
            if (tid < s) red[tid] += red[tid + s];
            __syncthreads();
        }
        if (tid == 0) out[dseg] = red[0] + bm2[0];
        __syncthreads();
    }
}

// ---------------------------------------------------------------------------
extern "C" void kernel_launch(void* const* d_in, const int* in_sizes, int n_in,
                              void* d_out, int out_size)
{
    const float4* emb4   = (const float4*)d_in[0];
    const int*    batch  = (const int*)  d_in[1];
    const float*  W_lins = (const float*)d_in[2];
    const float*  b_lins = (const float*)d_in[3];
    const float*  W1     = (const float*)d_in[4];
    const float*  b1     = (const float*)d_in[5];
    const float*  W2     = (const float*)d_in[6];
    const float*  b2     = (const float*)d_in[7];
    const float*  Wm1    = (const float*)d_in[8];
    const float*  bm1    = (const float*)d_in[9];
    const float*  Wm2    = (const float*)d_in[10];
    const float*  bm2    = (const float*)d_in[11];
    float* out = (float*)d_out;

    static int nsm = 0;
    if (nsm == 0) {
        cudaDeviceGetAttribute(&nsm, cudaDevAttrMultiProcessorCount, 0);
        if (nsm <= 0) nsm = 148;
        cudaFuncSetAttribute(k_node, cudaFuncAttributeMaxDynamicSharedMemorySize, SMEM_K1);
    }

    k_node<<<nsm, 512, SMEM_K1>>>(emb4, W_lins, b_lins, W1, b1, W2, b2);
    k_agg<<<B_SEG / 8, 256>>>(batch, Wm1, bm1, Wm2, bm2, out);
}